// round 16
// baseline (speedup 1.0000x reference)
#include <cuda_runtime.h>
#include <cuda_fp16.h>
#include <cstdint>
#include <math.h>

#define Bn   2
#define Ln   1024
#define Dn   1024
#define Hn   16
#define HDn  64
#define HIDn 4096
#define Mn   (Bn*Ln)        /* 2048 rows */
#define EPSc 1e-6f
#define SCALEc 0.125f       /* 64^-0.5 */

// ---------------- scratch (device globals; no runtime allocation) ----------
__device__ __half g_h16r[Mn*Dn],  g_h16i[Mn*Dn];
__device__ __half g_q16r[Mn*Dn],  g_q16i[Mn*Dn];
__device__ __half g_k16r[Mn*Dn],  g_k16i[Mn*Dn];
__device__ __half g_v16r[Mn*Dn],  g_v16i[Mn*Dn];
__device__ __half g_ao16r[Mn*Dn], g_ao16i[Mn*Dn];
__device__ float  g_ar[Mn*Dn],  g_ai[Mn*Dn];
__device__ __half g_f16r[Mn*HIDn], g_f16i[Mn*HIDn];
// half weight copies
__device__ __half g_wq16r[Dn*Dn],   g_wq16i[Dn*Dn];
__device__ __half g_wk16r[Dn*Dn],   g_wk16i[Dn*Dn];
__device__ __half g_wv16r[Dn*Dn],   g_wv16i[Dn*Dn];
__device__ __half g_wo16r[Dn*Dn],   g_wo16i[Dn*Dn];
__device__ __half g_w116r[HIDn*Dn], g_w116i[HIDn*Dn];
__device__ __half g_w216r[Dn*HIDn], g_w216i[Dn*HIDn];

// ================= helpers (baseline PTX only) ==============================
__device__ __forceinline__ uint32_t smem_u32(const void* p) {
    uint32_t a;
    asm("{ .reg .u64 t; cvta.to.shared.u64 t, %1; cvt.u32.u64 %0, t; }" : "=r"(a) : "l"(p));
    return a;
}
#define CP16(dst_u32, src_ptr) \
    asm volatile("cp.async.cg.shared.global [%0], [%1], 16;" :: "r"(dst_u32), "l"(src_ptr) : "memory")
#define CP_COMMIT() asm volatile("cp.async.commit_group;" ::: "memory")
#define CP_WAIT1()  asm volatile("cp.async.wait_group 1;" ::: "memory")
#define CP_WAIT0()  asm volatile("cp.async.wait_group 0;" ::: "memory")

#define MMA_F16(d, a, b) \
    asm volatile("mma.sync.aligned.m16n8k16.row.col.f32.f16.f16.f32 " \
        "{%0,%1,%2,%3}, {%4,%5,%6,%7}, {%8,%9}, {%0,%1,%2,%3};" \
        : "+f"((d)[0]), "+f"((d)[1]), "+f"((d)[2]), "+f"((d)[3]) \
        : "r"((a)[0]), "r"((a)[1]), "r"((a)[2]), "r"((a)[3]), \
          "r"((b)[0]), "r"((b)[1]))

#define LDSM4(r, addr) \
    asm volatile("ldmatrix.sync.aligned.m8n8.x4.shared.b16 {%0,%1,%2,%3}, [%4];" \
        : "=r"((r)[0]), "=r"((r)[1]), "=r"((r)[2]), "=r"((r)[3]) : "r"(addr))
#define LDSM4T(r, addr) \
    asm volatile("ldmatrix.sync.aligned.m8n8.x4.trans.shared.b16 {%0,%1,%2,%3}, [%4];" \
        : "=r"((r)[0]), "=r"((r)[1]), "=r"((r)[2]), "=r"((r)[3]) : "r"(addr))

__device__ __forceinline__ uint32_t packh2(float lo, float hi) {
    __half2 h = __floats2half2_rn(lo, hi);
    return *reinterpret_cast<uint32_t*>(&h);
}

// ================= weight prep: fp32 -> fp16 rn ==============================
__global__ void wprep16(const float4* __restrict__ wr, const float4* __restrict__ wi,
                        __half2* __restrict__ owr, __half2* __restrict__ owi, int n4)
{
    int i = blockIdx.x * 256 + threadIdx.x;
    if (i >= n4) return;
    float4 r = wr[i], m = wi[i];
    owr[2*i]   = __floats2half2_rn(r.x, r.y);
    owr[2*i+1] = __floats2half2_rn(r.z, r.w);
    owi[2*i]   = __floats2half2_rn(m.x, m.y);
    owi[2*i+1] = __floats2half2_rn(m.z, m.w);
}

// ================= complex GEMM fp16: 128x128 block, warp 32x64 =============
// C = A @ B^T (complex). A:[M,K], B:[N,K] half row-major. BK=64.
// 8 warps (4m x 2n). Per k-step: 12 ldmatrix / 64 mma.
// Epilogue modes: (a) half out; (b) fp32 + bias + residual; (c) modrelu->half.
#define BMg 128
#define BNg 128
#define BKg 64
#define LDKh 72
#define T_TILE_B (128*LDKh*2)          /* 18432 per 128-row tile */
#define OFF_AR 0
#define OFF_AI (T_TILE_B)
#define OFF_BR (2*T_TILE_B)
#define OFF_BI (3*T_TILE_B)
#define STG_BYTES (4*T_TILE_B)         /* 73728 */
#define SMEM_GEMM (2*STG_BYTES)        /* 147456 */

__global__ __launch_bounds__(256, 1)
void hgemm(const __half* __restrict__ Ar, const __half* __restrict__ Ai,
           const __half* __restrict__ Br, const __half* __restrict__ Bi,
           float* __restrict__ Cr, float* __restrict__ Ci,
           __half* __restrict__ Crh, __half* __restrict__ Cih,
           int M, int N, int K,
           const float* __restrict__ biasr, const float* __restrict__ biasi,
           const float* __restrict__ resr,  const float* __restrict__ resi,
           const float* __restrict__ mb)
{
    extern __shared__ char smemc[];
    const uint32_t sb = smem_u32(smemc);
    const int tid = threadIdx.x;
    const int wid = tid >> 5, lane = tid & 31;
    const int g = lane >> 2, t4 = lane & 3;
    const int wm = wid & 3, wn = wid >> 2;
    const int bm = blockIdx.y * BMg, bn = blockIdx.x * BNg;
    const int row8 = tid >> 3, c8 = (tid & 7) * 8;

    const uint32_t a_base = (uint32_t)(((wm*32 + (lane & 15)) * LDKh + (lane >> 4) * 8) * 2);
    const uint32_t b_base = (uint32_t)(((wn*64 + (lane & 7) + ((lane >> 4) ? 8 : 0)) * LDKh
                                        + ((lane >> 3) & 1) * 8) * 2);

    float accR[2][8][4], accI[2][8][4];
#pragma unroll
    for (int mt = 0; mt < 2; mt++)
#pragma unroll
        for (int nt = 0; nt < 8; nt++)
#pragma unroll
            for (int r = 0; r < 4; r++) { accR[mt][nt][r] = 0.f; accI[mt][nt][r] = 0.f; }

    const int nch = K / BKg;
    auto prefetch = [&](int ch) {
        const uint32_t dst = sb + (uint32_t)((ch & 1) * STG_BYTES);
        const int k0 = ch * BKg;
#pragma unroll
        for (int j = 0; j < 4; j++) {
            const int row = row8 + j * 32;
            const uint32_t o = (uint32_t)((row * LDKh + c8) * 2);
            const size_t ga = (size_t)(bm + row) * K + k0 + c8;
            const size_t gb = (size_t)(bn + row) * K + k0 + c8;
            CP16(dst + OFF_AR + o, Ar + ga);
            CP16(dst + OFF_AI + o, Ai + ga);
            CP16(dst + OFF_BR + o, Br + gb);
            CP16(dst + OFF_BI + o, Bi + gb);
        }
    };

    prefetch(0);
    CP_COMMIT();
    for (int ch = 0; ch < nch; ch++) {
        if (ch + 1 < nch) prefetch(ch + 1);
        CP_COMMIT();
        CP_WAIT1();
        __syncthreads();
        const uint32_t su = sb + (uint32_t)((ch & 1) * STG_BYTES);
#pragma unroll
        for (int ks = 0; ks < 4; ks++) {
            const uint32_t ko = (uint32_t)(ks * 32);
            uint32_t afr[2][4], afi[2][4];
#pragma unroll
            for (int mt = 0; mt < 2; mt++) {
                const uint32_t ao = su + a_base + (uint32_t)(mt * 16 * LDKh * 2) + ko;
                LDSM4(afr[mt], ao + OFF_AR);
                LDSM4(afi[mt], ao + OFF_AI);
            }
            uint32_t br_[8][2], bi_[8][2];
#pragma unroll
            for (int ng = 0; ng < 4; ng++) {
                const uint32_t bo = su + b_base + (uint32_t)(ng * 16 * LDKh * 2) + ko;
                uint32_t t[4];
                LDSM4(t, bo + OFF_BR);
                br_[2*ng][0]=t[0]; br_[2*ng][1]=t[1]; br_[2*ng+1][0]=t[2]; br_[2*ng+1][1]=t[3];
                LDSM4(t, bo + OFF_BI);
                bi_[2*ng][0]=t[0]; bi_[2*ng][1]=t[1]; bi_[2*ng+1][0]=t[2]; bi_[2*ng+1][1]=t[3];
            }
#pragma unroll
            for (int mt = 0; mt < 2; mt++) {
                uint32_t afn[4];
#pragma unroll
                for (int r = 0; r < 4; r++) afn[r] = afi[mt][r] ^ 0x80008000u;
#pragma unroll
                for (int nt = 0; nt < 8; nt++) {
                    MMA_F16(accR[mt][nt], afr[mt], br_[nt]);
                    MMA_F16(accR[mt][nt], afn,     bi_[nt]);
                    MMA_F16(accI[mt][nt], afr[mt], bi_[nt]);
                    MMA_F16(accI[mt][nt], afi[mt], br_[nt]);
                }
            }
        }
        __syncthreads();
    }

#pragma unroll
    for (int mt = 0; mt < 2; mt++) {
#pragma unroll
        for (int rh = 0; rh < 2; rh++) {
            const int row = bm + wm*32 + mt*16 + g + rh*8;
#pragma unroll
            for (int nt = 0; nt < 8; nt++) {
                const int col = bn + wn*64 + nt*8 + 2*t4;
                float vr0 = accR[mt][nt][rh*2],   vr1 = accR[mt][nt][rh*2+1];
                float vi0 = accI[mt][nt][rh*2],   vi1 = accI[mt][nt][rh*2+1];
                if (biasr) {
                    vr0 += biasr[col]; vr1 += biasr[col+1];
                    vi0 += biasi[col]; vi1 += biasi[col+1];
                }
                if (mb) {                       // fused ModReLU -> half
                    const float b0 = mb[col], b1 = mb[col+1];
                    float mag0 = sqrtf(vr0*vr0 + vi0*vi0);
                    float mag1 = sqrtf(vr1*vr1 + vi1*vi1);
                    float fac0 = fmaxf(mag0 + b0, 0.f) / (mag0 > 0.f ? mag0 : 1.f);
                    float fac1 = fmaxf(mag1 + b1, 0.f) / (mag1 > 0.f ? mag1 : 1.f);
                    *(__half2*)(Crh + (size_t)row*N + col) = __floats2half2_rn(vr0*fac0, vr1*fac1);
                    *(__half2*)(Cih + (size_t)row*N + col) = __floats2half2_rn(vi0*fac0, vi1*fac1);
                } else if (Crh) {
                    *(__half2*)(Crh + (size_t)row*N + col) = __floats2half2_rn(vr0, vr1);
                    *(__half2*)(Cih + (size_t)row*N + col) = __floats2half2_rn(vi0, vi1);
                } else {
                    if (resr) {
                        const float2 rr = *(const float2*)(resr + (size_t)row*N + col);
                        const float2 ri = *(const float2*)(resi + (size_t)row*N + col);
                        vr0 += rr.x; vr1 += rr.y; vi0 += ri.x; vi1 += ri.y;
                    }
                    *(float2*)(Cr + (size_t)row*N + col) = make_float2(vr0, vr1);
                    *(float2*)(Ci + (size_t)row*N + col) = make_float2(vi0, vi1);
                }
            }
        }
    }
}

// ================= fused flash attention (unchanged winner from R13) ========
#define FLD 72
#define FQT_B (128*FLD*2)
#define FKV_B (4*FQT_B)
#define SMEM_FA (2*FQT_B + 2*FKV_B)

__global__ __launch_bounds__(256, 1)
void flash16(const __half* __restrict__ Q_r, const __half* __restrict__ Q_i,
             const __half* __restrict__ K_r, const __half* __restrict__ K_i,
             const __half* __restrict__ V_r, const __half* __restrict__ V_i,
             __half* __restrict__ Or, __half* __restrict__ Oi)
{
    const int bh = blockIdx.y;
    const int tile = blockIdx.x;
    const int bm = tile * 128;
    const size_t off = (size_t)(bh >> 4) * Ln * Dn + (size_t)(bh & 15) * HDn;
    extern __shared__ char smemc[];
    const uint32_t sb = smem_u32(smemc);
    const uint32_t qb = sb;

    const int tid = threadIdx.x;
    const int wid = tid >> 5, lane = tid & 31;
    const int g = lane >> 2, t4 = lane & 3;
    const int row8 = tid >> 3, c8 = (tid & 7) * 8;

#pragma unroll
    for (int j = 0; j < 4; j++) {
        const int row = row8 + j * 32;
        const uint32_t o = (uint32_t)((row * FLD + c8) * 2);
        const size_t gq = off + (size_t)(bm + row) * Dn + c8;
        CP16(qb + o,          Q_r + gq);
        CP16(qb + FQT_B + o,  Q_i + gq);
    }
    auto prefetch_kv = [&](int kt) {
        const uint32_t dst = sb + 2*FQT_B + (uint32_t)((kt & 1) * FKV_B);
#pragma unroll
        for (int j = 0; j < 4; j++) {
            const int row = row8 + j * 32;
            const uint32_t o = (uint32_t)((row * FLD + c8) * 2);
            const size_t gk = off + (size_t)(kt*128 + row) * Dn + c8;
            CP16(dst + o,           K_r + gk);
            CP16(dst + FQT_B + o,   K_i + gk);
            CP16(dst + 2*FQT_B + o, V_r + gk);
            CP16(dst + 3*FQT_B + o, V_i + gk);
        }
    };
    prefetch_kv(0);
    CP_COMMIT();
    CP_WAIT0();
    __syncthreads();

    const uint32_t aq_base = (uint32_t)(((wid*16 + (lane & 15)) * FLD + (lane >> 4) * 8) * 2);
    uint32_t aqr[4][4], aqi[4][4];
#pragma unroll
    for (int ks = 0; ks < 4; ks++) {
        LDSM4(aqr[ks], qb + aq_base + (uint32_t)(ks * 32));
        LDSM4(aqi[ks], qb + FQT_B + aq_base + (uint32_t)(ks * 32));
    }

    const uint32_t bk_base = (uint32_t)((((lane & 7) + ((lane >> 4) ? 8 : 0)) * FLD
                                         + ((lane >> 3) & 1) * 8) * 2);
    const uint32_t bv_base = (uint32_t)((((lane & 7) + ((lane >> 3) & 1) * 8) * FLD
                                         + (lane >> 4) * 8) * 2);

    float oR[8][4], oI[8][4];
#pragma unroll
    for (int nt = 0; nt < 8; nt++)
#pragma unroll
        for (int r = 0; r < 4; r++) { oR[nt][r] = 0.f; oI[nt][r] = 0.f; }
    float m0 = -1e30f, m1 = -1e30f, s0 = 0.f, s1 = 0.f;

    const int row0 = bm + wid*16 + g;
    const int row1 = row0 + 8;

    for (int kt = 0; kt <= tile; kt++) {
        if (kt < tile) { prefetch_kv(kt + 1); CP_COMMIT(); }
        const uint32_t kvb = sb + 2*FQT_B + (uint32_t)((kt & 1) * FKV_B);

        float sacc[16][4];
#pragma unroll
        for (int nt = 0; nt < 16; nt++)
#pragma unroll
            for (int r = 0; r < 4; r++) sacc[nt][r] = 0.f;
#pragma unroll
        for (int ks = 0; ks < 4; ks++) {
            const uint32_t ko = (uint32_t)(ks * 32);
#pragma unroll
            for (int ng = 0; ng < 8; ng++) {
                const uint32_t bo = kvb + bk_base + (uint32_t)(ng * 16 * FLD * 2) + ko;
                uint32_t tkr[4], tki[4];
                LDSM4(tkr, bo);
                LDSM4(tki, bo + FQT_B);
                uint32_t blo[2] = {tkr[0], tkr[1]}, bhi[2] = {tkr[2], tkr[3]};
                MMA_F16(sacc[2*ng],   aqr[ks], blo);
                MMA_F16(sacc[2*ng+1], aqr[ks], bhi);
                blo[0] = tki[0]; blo[1] = tki[1]; bhi[0] = tki[2]; bhi[1] = tki[3];
                MMA_F16(sacc[2*ng],   aqi[ks], blo);
                MMA_F16(sacc[2*ng+1], aqi[ks], bhi);
            }
        }
        if (kt == tile) {
#pragma unroll
            for (int nt = 0; nt < 16; nt++) {
                const int c0 = kt*128 + nt*8 + 2*t4;
                sacc[nt][0] = (c0   <= row0) ? sacc[nt][0]*SCALEc : -1e30f;
                sacc[nt][1] = (c0+1 <= row0) ? sacc[nt][1]*SCALEc : -1e30f;
                sacc[nt][2] = (c0   <= row1) ? sacc[nt][2]*SCALEc : -1e30f;
                sacc[nt][3] = (c0+1 <= row1) ? sacc[nt][3]*SCALEc : -1e30f;
            }
        } else {
#pragma unroll
            for (int nt = 0; nt < 16; nt++)
#pragma unroll
                for (int r = 0; r < 4; r++) sacc[nt][r] *= SCALEc;
        }

        float mx0 = -1e30f, mx1 = -1e30f;
#pragma unroll
        for (int nt = 0; nt < 16; nt++) {
            mx0 = fmaxf(mx0, fmaxf(sacc[nt][0], sacc[nt][1]));
            mx1 = fmaxf(mx1, fmaxf(sacc[nt][2], sacc[nt][3]));
        }
        mx0 = fmaxf(mx0, __shfl_xor_sync(0xffffffffu, mx0, 1));
        mx0 = fmaxf(mx0, __shfl_xor_sync(0xffffffffu, mx0, 2));
        mx1 = fmaxf(mx1, __shfl_xor_sync(0xffffffffu, mx1, 1));
        mx1 = fmaxf(mx1, __shfl_xor_sync(0xffffffffu, mx1, 2));
        const float nm0 = fmaxf(m0, mx0), nm1 = fmaxf(m1, mx1);
        const float f0 = expf(m0 - nm0), f1 = expf(m1 - nm1);
        float sum0 = 0.f, sum1 = 0.f;
#pragma unroll
        for (int nt = 0; nt < 16; nt++) {
            sacc[nt][0] = expf(sacc[nt][0] - nm0);
            sacc[nt][1] = expf(sacc[nt][1] - nm0);
            sacc[nt][2] = expf(sacc[nt][2] - nm1);
            sacc[nt][3] = expf(sacc[nt][3] - nm1);
            sum0 += sacc[nt][0] + sacc[nt][1];
            sum1 += sacc[nt][2] + sacc[nt][3];
        }
        sum0 += __shfl_xor_sync(0xffffffffu, sum0, 1);
        sum0 += __shfl_xor_sync(0xffffffffu, sum0, 2);
        sum1 += __shfl_xor_sync(0xffffffffu, sum1, 1);
        sum1 += __shfl_xor_sync(0xffffffffu, sum1, 2);
        s0 = s0 * f0 + sum0;
        s1 = s1 * f1 + sum1;
        m0 = nm0; m1 = nm1;
#pragma unroll
        for (int nt = 0; nt < 8; nt++) {
            oR[nt][0] *= f0; oR[nt][1] *= f0; oR[nt][2] *= f1; oR[nt][3] *= f1;
            oI[nt][0] *= f0; oI[nt][1] *= f0; oI[nt][2] *= f1; oI[nt][3] *= f1;
        }

#pragma unroll
        for (int kc = 0; kc < 8; kc++) {
            uint32_t pa[4];
            pa[0] = packh2(sacc[2*kc][0],   sacc[2*kc][1]);
            pa[1] = packh2(sacc[2*kc][2],   sacc[2*kc][3]);
            pa[2] = packh2(sacc[2*kc+1][0], sacc[2*kc+1][1]);
            pa[3] = packh2(sacc[2*kc+1][2], sacc[2*kc+1][3]);
            const uint32_t vrow = bv_base + (uint32_t)(kc * 16 * FLD * 2);
#pragma unroll
            for (int vg = 0; vg < 2; vg++) {
                const uint32_t bo = kvb + vrow + (uint32_t)(vg * 32 * 2);
                uint32_t tvr[4], tvi[4];
                LDSM4T(tvr, bo + 2*FQT_B);
                LDSM4T(tvi, bo + 3*FQT_B);
                uint32_t blo[2] = {tvr[0], tvr[1]}, bhi[2] = {tvr[2], tvr[3]};
                MMA_F16(oR[4*vg],   pa, blo);
                MMA_F16(oR[4*vg+1], pa, bhi);
                blo[0] = tvi[0]; blo[1] = tvi[1]; bhi[0] = tvi[2]; bhi[1] = tvi[3];
                MMA_F16(oI[4*vg],   pa, blo);
                MMA_F16(oI[4*vg+1], pa, bhi);
            }
#pragma unroll
            for (int vg = 0; vg < 2; vg++) {
                const uint32_t bo = kvb + vrow + (uint32_t)((vg * 32 + 16) * 2);
                uint32_t tvr[4], tvi[4];
                LDSM4T(tvr, bo + 2*FQT_B);
                LDSM4T(tvi, bo + 3*FQT_B);
                uint32_t blo[2] = {tvr[0], tvr[1]}, bhi[2] = {tvr[2], tvr[3]};
                MMA_F16(oR[4*vg+2], pa, blo);
                MMA_F16(oR[4*vg+3], pa, bhi);
                blo[0] = tvi[0]; blo[1] = tvi[1]; bhi[0] = tvi[2]; bhi[1] = tvi[3];
                MMA_F16(oI[4*vg+2], pa, blo);
                MMA_F16(oI[4*vg+3], pa, bhi);
            }
        }
        if (kt < tile) CP_WAIT0();
        __syncthreads();
    }

    const float inv0 = 1.f / s0, inv1 = 1.f / s1;
#pragma unroll
    for (int nt = 0; nt < 8; nt++) {
        const int col = nt*8 + 2*t4;
        const size_t p0 = off + (size_t)row0 * Dn + col;
        const size_t p1 = off + (size_t)row1 * Dn + col;
        *(__half2*)(Or + p0) = __floats2half2_rn(oR[nt][0]*inv0, oR[nt][1]*inv0);
        *(__half2*)(Oi + p0) = __floats2half2_rn(oI[nt][0]*inv0, oI[nt][1]*inv0);
        *(__half2*)(Or + p1) = __floats2half2_rn(oR[nt][2]*inv1, oR[nt][3]*inv1);
        *(__half2*)(Oi + p1) = __floats2half2_rn(oI[nt][2]*inv1, oI[nt][3]*inv1);
    }
}

// ---------------- complex layernorm (fp32 in, half out) ---------------------
__global__ void cln16(const float* __restrict__ xr, const float* __restrict__ xi,
                      const float* __restrict__ gr, const float* __restrict__ gi,
                      const float* __restrict__ bre, const float* __restrict__ bim,
                      __half* __restrict__ outr, __half* __restrict__ outi)
{
    int row = blockIdx.x;
    const float* pr = xr + (size_t)row * Dn;
    const float* pi = xi + (size_t)row * Dn;
    __shared__ float s1[256], s2[256];
    int tid = threadIdx.x;
    float sr = 0.f, si = 0.f;
    for (int j = tid; j < Dn; j += 256) { sr += pr[j]; si += pi[j]; }
    s1[tid] = sr; s2[tid] = si;
    __syncthreads();
    for (int o = 128; o > 0; o >>= 1) {
        if (tid < o) { s1[tid] += s1[tid+o]; s2[tid] += s2[tid+o]; }
        __syncthreads();
    }
    float mr = s1[0] * (1.f/Dn), mi = s2[0] * (1.f/Dn);
    __syncthreads();
    float v = 0.f;
    for (int j = tid; j < Dn; j += 256) {
        float cr = pr[j] - mr, ci = pi[j] - mi;
        v += cr*cr + ci*ci;
    }
    s1[tid] = v;
    __syncthreads();
    for (int o = 128; o > 0; o >>= 1) {
        if (tid < o) s1[tid] += s1[tid+o];
        __syncthreads();
    }
    float inv = rsqrtf(s1[0] * (1.f/Dn) + EPSc);
    for (int j = tid; j < Dn; j += 256) {
        float nr = (pr[j]-mr)*inv, ni = (pi[j]-mi)*inv;
        outr[(size_t)row*Dn + j] = __float2half_rn(nr*gr[j] - ni*gi[j] + bre[j]);
        outi[(size_t)row*Dn + j] = __float2half_rn(nr*gi[j] + ni*gr[j] + bim[j]);
    }
}

// ---------------- RoPE (in place on half arrays) ----------------------------
__global__ void rope16(__half* __restrict__ xr, __half* __restrict__ xi)
{
    int idx = blockIdx.x * blockDim.x + threadIdx.x;
    int j = idx & 31;
    int t = idx >> 5;
    int h = t & (Hn-1); t >>= 4;
    int l = t & (Ln-1);
    int b = t >> 10;
    size_t base = ((size_t)(b*Ln + l)) * Dn + h * HDn;
    double invf = exp(-((double)(2*j) / (double)HDn) * 9.210340371976184);
    double th = (double)l * invf;
    double sd, cd;
    sincos(th, &sd, &cd);
    float c = (float)cd, s = (float)sd;
    float a0 = __half2float(xr[base+j]), a1 = __half2float(xr[base+j+32]);
    xr[base+j]    = __float2half_rn(a0*c - a1*s);
    xr[base+j+32] = __float2half_rn(a1*c + a0*s);
    float b0 = __half2float(xi[base+j]), b1 = __half2float(xi[base+j+32]);
    xi[base+j]    = __float2half_rn(b0*c - b1*s);
    xi[base+j+32] = __float2half_rn(b1*c + b0*s);
}

// ---------------- launch ----------------------------------------------------
extern "C" void kernel_launch(void* const* d_in, const int* in_sizes, int n_in,
                              void* d_out, int out_size)
{
    const float* x_r   = (const float*)d_in[0];
    const float* x_i   = (const float*)d_in[1];
    const float* Wq_r  = (const float*)d_in[2];
    const float* Wq_i  = (const float*)d_in[3];
    const float* Wk_r  = (const float*)d_in[4];
    const float* Wk_i  = (const float*)d_in[5];
    const float* Wv_r  = (const float*)d_in[6];
    const float* Wv_i  = (const float*)d_in[7];
    const float* Wo_r  = (const float*)d_in[8];
    const float* Wo_i  = (const float*)d_in[9];
    const float* bo_r  = (const float*)d_in[10];
    const float* bo_i  = (const float*)d_in[11];
    const float* ln1_gr = (const float*)d_in[12];
    const float* ln1_gi = (const float*)d_in[13];
    const float* ln1_br = (const float*)d_in[14];
    const float* ln1_bi = (const float*)d_in[15];
    const float* ln2_gr = (const float*)d_in[16];
    const float* ln2_gi = (const float*)d_in[17];
    const float* ln2_br = (const float*)d_in[18];
    const float* ln2_bi = (const float*)d_in[19];
    const float* W1_r  = (const float*)d_in[20];
    const float* W1_i  = (const float*)d_in[21];
    const float* b1_r  = (const float*)d_in[22];
    const float* b1_i  = (const float*)d_in[23];
    const float* W2_r  = (const float*)d_in[24];
    const float* W2_i  = (const float*)d_in[25];
    const float* b2_r  = (const float*)d_in[26];
    const float* b2_i  = (const float*)d_in[27];
    const float* mod_b = (const float*)d_in[28];
    float* out = (float*)d_out;

    __half *h16r, *h16i, *q16r, *q16i, *k16r, *k16i, *v16r, *v16i;
    __half *ao16r, *ao16i, *f16r, *f16i;
    __half *wq16r, *wq16i, *wk16r, *wk16i, *wv16r, *wv16i, *wo16r, *wo16i;
    __half *w116r, *w116i, *w216r, *w216i;
    float *ar, *ai;
    cudaGetSymbolAddress((void**)&h16r, g_h16r);  cudaGetSymbolAddress((void**)&h16i, g_h16i);
    cudaGetSymbolAddress((void**)&q16r, g_q16r);  cudaGetSymbolAddress((void**)&q16i, g_q16i);
    cudaGetSymbolAddress((void**)&k16r, g_k16r);  cudaGetSymbolAddress((void**)&k16i, g_k16i);
    cudaGetSymbolAddress((void**)&v16r, g_v16r);  cudaGetSymbolAddress((void**)&v16i, g_v16i);
    cudaGetSymbolAddress((void**)&ao16r, g_ao16r);cudaGetSymbolAddress((void**)&ao16i, g_ao16i);
    cudaGetSymbolAddress((void**)&ar, g_ar);      cudaGetSymbolAddress((void**)&ai, g_ai);
    cudaGetSymbolAddress((void**)&f16r, g_f16r);  cudaGetSymbolAddress((void**)&f16i, g_f16i);
    cudaGetSymbolAddress((void**)&wq16r, g_wq16r);cudaGetSymbolAddress((void**)&wq16i, g_wq16i);
    cudaGetSymbolAddress((void**)&wk16r, g_wk16r);cudaGetSymbolAddress((void**)&wk16i, g_wk16i);
    cudaGetSymbolAddress((void**)&wv16r, g_wv16r);cudaGetSymbolAddress((void**)&wv16i, g_wv16i);
    cudaGetSymbolAddress((void**)&wo16r, g_wo16r);cudaGetSymbolAddress((void**)&wo16i, g_wo16i);
    cudaGetSymbolAddress((void**)&w116r, g_w116r);cudaGetSymbolAddress((void**)&w116i, g_w116i);
    cudaGetSymbolAddress((void**)&w216r, g_w216r);cudaGetSymbolAddress((void**)&w216i, g_w216i);

    cudaFuncSetAttribute(hgemm,   cudaFuncAttributeMaxDynamicSharedMemorySize, SMEM_GEMM);
    cudaFuncSetAttribute(flash16, cudaFuncAttributeMaxDynamicSharedMemorySize, SMEM_FA);

    // 0. weight conversion to fp16
    const int n4d = Dn*Dn/4, n4h = HIDn*Dn/4;
    wprep16<<<n4d/256, 256>>>((const float4*)Wq_r, (const float4*)Wq_i, (__half2*)wq16r, (__half2*)wq16i, n4d);
    wprep16<<<n4d/256, 256>>>((const float4*)Wk_r, (const float4*)Wk_i, (__half2*)wk16r, (__half2*)wk16i, n4d);
    wprep16<<<n4d/256, 256>>>((const float4*)Wv_r, (const float4*)Wv_i, (__half2*)wv16r, (__half2*)wv16i, n4d);
    wprep16<<<n4d/256, 256>>>((const float4*)Wo_r, (const float4*)Wo_i, (__half2*)wo16r, (__half2*)wo16i, n4d);
    wprep16<<<n4h/256, 256>>>((const float4*)W1_r, (const float4*)W1_i, (__half2*)w116r, (__half2*)w116i, n4h);
    wprep16<<<n4h/256, 256>>>((const float4*)W2_r, (const float4*)W2_i, (__half2*)w216r, (__half2*)w216i, n4h);

    // 1. LN1 -> half
    cln16<<<Mn, 256>>>(x_r, x_i, ln1_gr, ln1_gi, ln1_br, ln1_bi, h16r, h16i);

    // 2. QKV projections (half in, half out)
    dim3 gproj(Dn/BNg, Mn/BMg);      /* (8, 16) */
    hgemm<<<gproj, 256, SMEM_GEMM>>>(h16r, h16i, wq16r, wq16i, nullptr, nullptr, q16r, q16i, Mn, Dn, Dn, nullptr, nullptr, nullptr, nullptr, nullptr);
    hgemm<<<gproj, 256, SMEM_GEMM>>>(h16r, h16i, wk16r, wk16i, nullptr, nullptr, k16r, k16i, Mn, Dn, Dn, nullptr, nullptr, nullptr, nullptr, nullptr);
    hgemm<<<gproj, 256, SMEM_GEMM>>>(h16r, h16i, wv16r, wv16i, nullptr, nullptr, v16r, v16i, Mn, Dn, Dn, nullptr, nullptr, nullptr, nullptr, nullptr);

    // 3. RoPE on Q and K (half in place)
    rope16<<<(Bn*Ln*Hn*32)/256, 256>>>(q16r, q16i);
    rope16<<<(Bn*Ln*Hn*32)/256, 256>>>(k16r, k16i);

    // 4. fused flash attention -> ao16
    flash16<<<dim3(Ln/128, Bn*Hn), 256, SMEM_FA>>>(q16r, q16i, k16r, k16i, v16r, v16i, ao16r, ao16i);

    // 5. out projection + bias + residual(x) -> fp32
    hgemm<<<gproj, 256, SMEM_GEMM>>>(ao16r, ao16i, wo16r, wo16i, ar, ai, nullptr, nullptr, Mn, Dn, Dn, bo_r, bo_i, x_r, x_i, nullptr);

    // 6. LN2 -> half
    cln16<<<Mn, 256>>>(ar, ai, ln2_gr, ln2_gi, ln2_br, ln2_bi, h16r, h16i);

    // 7. FC1 + bias + fused ModReLU -> half
    hgemm<<<dim3(HIDn/BNg, Mn/BMg), 256, SMEM_GEMM>>>(h16r, h16i, w116r, w116i, nullptr, nullptr, f16r, f16i, Mn, HIDn, Dn, b1_r, b1_i, nullptr, nullptr, mod_b);

    // 8. FC2 + bias + residual(ar/ai) -> output (fp32)
    hgemm<<<gproj, 256, SMEM_GEMM>>>(f16r, f16i, w216r, w216i, out, out + (size_t)Mn*Dn, nullptr, nullptr, Mn, Dn, HIDn, b2_r, b2_i, ar, ai, nullptr);
}

// round 17
// speedup vs baseline: 1.0409x; 1.0409x over previous
#include <cuda_runtime.h>
#include <cuda_fp16.h>
#include <cstdint>
#include <math.h>

#define Bn   2
#define Ln   1024
#define Dn   1024
#define Hn   16
#define HDn  64
#define HIDn 4096
#define Mn   (Bn*Ln)        /* 2048 rows */
#define EPSc 1e-6f
#define SCALEc 0.125f       /* 64^-0.5 */

// ---------------- scratch (device globals; no runtime allocation) ----------
__device__ __half g_h16r[Mn*Dn],  g_h16i[Mn*Dn];
__device__ __half g_q16r[Mn*Dn],  g_q16i[Mn*Dn];
__device__ __half g_k16r[Mn*Dn],  g_k16i[Mn*Dn];
__device__ __half g_v16r[Mn*Dn],  g_v16i[Mn*Dn];
__device__ __half g_ao16r[Mn*Dn], g_ao16i[Mn*Dn];
__device__ float  g_ar[Mn*Dn],  g_ai[Mn*Dn];
__device__ __half g_f16r[Mn*HIDn], g_f16i[Mn*HIDn];
// half weight copies
__device__ __half g_wq16r[Dn*Dn],   g_wq16i[Dn*Dn];
__device__ __half g_wk16r[Dn*Dn],   g_wk16i[Dn*Dn];
__device__ __half g_wv16r[Dn*Dn],   g_wv16i[Dn*Dn];
__device__ __half g_wo16r[Dn*Dn],   g_wo16i[Dn*Dn];
__device__ __half g_w116r[HIDn*Dn], g_w116i[HIDn*Dn];
__device__ __half g_w216r[Dn*HIDn], g_w216i[Dn*HIDn];

// ================= helpers (baseline PTX only) ==============================
__device__ __forceinline__ uint32_t smem_u32(const void* p) {
    uint32_t a;
    asm("{ .reg .u64 t; cvta.to.shared.u64 t, %1; cvt.u32.u64 %0, t; }" : "=r"(a) : "l"(p));
    return a;
}
#define CP16(dst_u32, src_ptr) \
    asm volatile("cp.async.cg.shared.global [%0], [%1], 16;" :: "r"(dst_u32), "l"(src_ptr) : "memory")
#define CP_COMMIT() asm volatile("cp.async.commit_group;" ::: "memory")
#define CP_WAIT1()  asm volatile("cp.async.wait_group 1;" ::: "memory")
#define CP_WAIT0()  asm volatile("cp.async.wait_group 0;" ::: "memory")

#define MMA_F16(d, a, b) \
    asm volatile("mma.sync.aligned.m16n8k16.row.col.f32.f16.f16.f32 " \
        "{%0,%1,%2,%3}, {%4,%5,%6,%7}, {%8,%9}, {%0,%1,%2,%3};" \
        : "+f"((d)[0]), "+f"((d)[1]), "+f"((d)[2]), "+f"((d)[3]) \
        : "r"((a)[0]), "r"((a)[1]), "r"((a)[2]), "r"((a)[3]), \
          "r"((b)[0]), "r"((b)[1]))

#define LDSM4(r, addr) \
    asm volatile("ldmatrix.sync.aligned.m8n8.x4.shared.b16 {%0,%1,%2,%3}, [%4];" \
        : "=r"((r)[0]), "=r"((r)[1]), "=r"((r)[2]), "=r"((r)[3]) : "r"(addr))
#define LDSM4T(r, addr) \
    asm volatile("ldmatrix.sync.aligned.m8n8.x4.trans.shared.b16 {%0,%1,%2,%3}, [%4];" \
        : "=r"((r)[0]), "=r"((r)[1]), "=r"((r)[2]), "=r"((r)[3]) : "r"(addr))

__device__ __forceinline__ uint32_t packh2(float lo, float hi) {
    __half2 h = __floats2half2_rn(lo, hi);
    return *reinterpret_cast<uint32_t*>(&h);
}

// ================= weight prep: fp32 -> fp16 rn ==============================
__global__ void wprep16(const float4* __restrict__ wr, const float4* __restrict__ wi,
                        __half2* __restrict__ owr, __half2* __restrict__ owi, int n4)
{
    int i = blockIdx.x * 256 + threadIdx.x;
    if (i >= n4) return;
    float4 r = wr[i], m = wi[i];
    owr[2*i]   = __floats2half2_rn(r.x, r.y);
    owr[2*i+1] = __floats2half2_rn(r.z, r.w);
    owi[2*i]   = __floats2half2_rn(m.x, m.y);
    owi[2*i+1] = __floats2half2_rn(m.z, m.w);
}

// ================= complex GEMM fp16 (R13 winner config + modrelu epi) ======
// C = A @ B^T (complex). A:[M,K], B:[N,K] half row-major.
// Block 128x64, BK=64 halves, 8 warps (4m x 2n), warp tile 32x32, occ 2.
#define BMg 128
#define BNg 64
#define BKg 64
#define LDKh 72
#define A_TILE_B (BMg*LDKh*2)
#define B_TILE_B (BNg*LDKh*2)
#define OFF_AR 0
#define OFF_AI (A_TILE_B)
#define OFF_BR (2*A_TILE_B)
#define OFF_BI (2*A_TILE_B + B_TILE_B)
#define STG_BYTES (2*A_TILE_B + 2*B_TILE_B)
#define SMEM_GEMM (2*STG_BYTES)

__global__ __launch_bounds__(256, 2)
void hgemm(const __half* __restrict__ Ar, const __half* __restrict__ Ai,
           const __half* __restrict__ Br, const __half* __restrict__ Bi,
           float* __restrict__ Cr, float* __restrict__ Ci,
           __half* __restrict__ Crh, __half* __restrict__ Cih,
           int M, int N, int K,
           const float* __restrict__ biasr, const float* __restrict__ biasi,
           const float* __restrict__ resr,  const float* __restrict__ resi,
           const float* __restrict__ mb)
{
    extern __shared__ char smemc[];
    const uint32_t sb = smem_u32(smemc);
    const int tid = threadIdx.x;
    const int wid = tid >> 5, lane = tid & 31;
    const int g = lane >> 2, t4 = lane & 3;
    const int wm = wid & 3, wn = wid >> 2;
    const int bm = blockIdx.y * BMg, bn = blockIdx.x * BNg;
    const int row8 = tid >> 3, c8 = (tid & 7) * 8;

    const uint32_t a_base = (uint32_t)(((wm*32 + (lane & 15)) * LDKh + (lane >> 4) * 8) * 2);
    const uint32_t b_base = (uint32_t)(((wn*32 + (lane & 7) + ((lane >> 4) ? 8 : 0)) * LDKh
                                        + ((lane >> 3) & 1) * 8) * 2);

    float accR[2][4][4], accI[2][4][4];
#pragma unroll
    for (int mt = 0; mt < 2; mt++)
#pragma unroll
        for (int nt = 0; nt < 4; nt++)
#pragma unroll
            for (int r = 0; r < 4; r++) { accR[mt][nt][r] = 0.f; accI[mt][nt][r] = 0.f; }

    const int nch = K / BKg;
    auto prefetch = [&](int ch) {
        const uint32_t dst = sb + (uint32_t)((ch & 1) * STG_BYTES);
        const int k0 = ch * BKg;
#pragma unroll
        for (int j = 0; j < 4; j++) {
            const int row = row8 + j * 32;
            const uint32_t o = (uint32_t)((row * LDKh + c8) * 2);
            const size_t ga = (size_t)(bm + row) * K + k0 + c8;
            CP16(dst + OFF_AR + o, Ar + ga);
            CP16(dst + OFF_AI + o, Ai + ga);
        }
#pragma unroll
        for (int j = 0; j < 2; j++) {
            const int row = row8 + j * 32;
            const uint32_t o = (uint32_t)((row * LDKh + c8) * 2);
            const size_t gb = (size_t)(bn + row) * K + k0 + c8;
            CP16(dst + OFF_BR + o, Br + gb);
            CP16(dst + OFF_BI + o, Bi + gb);
        }
    };

    prefetch(0);
    CP_COMMIT();
    for (int ch = 0; ch < nch; ch++) {
        if (ch + 1 < nch) prefetch(ch + 1);
        CP_COMMIT();
        CP_WAIT1();
        __syncthreads();
        const uint32_t su = sb + (uint32_t)((ch & 1) * STG_BYTES);
#pragma unroll
        for (int ks = 0; ks < 4; ks++) {
            const uint32_t ko = (uint32_t)(ks * 32);
            uint32_t afr[2][4], afi[2][4];
#pragma unroll
            for (int mt = 0; mt < 2; mt++) {
                const uint32_t ao = su + a_base + (uint32_t)(mt * 16 * LDKh * 2) + ko;
                LDSM4(afr[mt], ao + OFF_AR);
                LDSM4(afi[mt], ao + OFF_AI);
            }
            uint32_t br_[4][2], bi_[4][2];
#pragma unroll
            for (int ng = 0; ng < 2; ng++) {
                const uint32_t bo = su + b_base + (uint32_t)(ng * 16 * LDKh * 2) + ko;
                uint32_t t[4];
                LDSM4(t, bo + OFF_BR);
                br_[2*ng][0]=t[0]; br_[2*ng][1]=t[1]; br_[2*ng+1][0]=t[2]; br_[2*ng+1][1]=t[3];
                LDSM4(t, bo + OFF_BI);
                bi_[2*ng][0]=t[0]; bi_[2*ng][1]=t[1]; bi_[2*ng+1][0]=t[2]; bi_[2*ng+1][1]=t[3];
            }
#pragma unroll
            for (int mt = 0; mt < 2; mt++) {
                uint32_t afn[4];
#pragma unroll
                for (int r = 0; r < 4; r++) afn[r] = afi[mt][r] ^ 0x80008000u;
#pragma unroll
                for (int nt = 0; nt < 4; nt++) {
                    MMA_F16(accR[mt][nt], afr[mt], br_[nt]);
                    MMA_F16(accR[mt][nt], afn,     bi_[nt]);
                    MMA_F16(accI[mt][nt], afr[mt], bi_[nt]);
                    MMA_F16(accI[mt][nt], afi[mt], br_[nt]);
                }
            }
        }
        __syncthreads();
    }

#pragma unroll
    for (int mt = 0; mt < 2; mt++) {
#pragma unroll
        for (int rh = 0; rh < 2; rh++) {
            const int row = bm + wm*32 + mt*16 + g + rh*8;
#pragma unroll
            for (int nt = 0; nt < 4; nt++) {
                const int col = bn + wn*32 + nt*8 + 2*t4;
                float vr0 = accR[mt][nt][rh*2],   vr1 = accR[mt][nt][rh*2+1];
                float vi0 = accI[mt][nt][rh*2],   vi1 = accI[mt][nt][rh*2+1];
                if (biasr) {
                    vr0 += biasr[col]; vr1 += biasr[col+1];
                    vi0 += biasi[col]; vi1 += biasi[col+1];
                }
                if (mb) {                       // fused ModReLU -> half
                    const float b0 = mb[col], b1 = mb[col+1];
                    float mag0 = sqrtf(vr0*vr0 + vi0*vi0);
                    float mag1 = sqrtf(vr1*vr1 + vi1*vi1);
                    float fac0 = fmaxf(mag0 + b0, 0.f) / (mag0 > 0.f ? mag0 : 1.f);
                    float fac1 = fmaxf(mag1 + b1, 0.f) / (mag1 > 0.f ? mag1 : 1.f);
                    *(__half2*)(Crh + (size_t)row*N + col) = __floats2half2_rn(vr0*fac0, vr1*fac1);
                    *(__half2*)(Cih + (size_t)row*N + col) = __floats2half2_rn(vi0*fac0, vi1*fac1);
                } else if (Crh) {
                    *(__half2*)(Crh + (size_t)row*N + col) = __floats2half2_rn(vr0, vr1);
                    *(__half2*)(Cih + (size_t)row*N + col) = __floats2half2_rn(vi0, vi1);
                } else {
                    if (resr) {
                        const float2 rr = *(const float2*)(resr + (size_t)row*N + col);
                        const float2 ri = *(const float2*)(resi + (size_t)row*N + col);
                        vr0 += rr.x; vr1 += rr.y; vi0 += ri.x; vi1 += ri.y;
                    }
                    *(float2*)(Cr + (size_t)row*N + col) = make_float2(vr0, vr1);
                    *(float2*)(Ci + (size_t)row*N + col) = make_float2(vi0, vi1);
                }
            }
        }
    }
}

// ================= fused flash attention (unchanged winner from R13) ========
#define FLD 72
#define FQT_B (128*FLD*2)
#define FKV_B (4*FQT_B)
#define SMEM_FA (2*FQT_B + 2*FKV_B)

__global__ __launch_bounds__(256, 1)
void flash16(const __half* __restrict__ Q_r, const __half* __restrict__ Q_i,
             const __half* __restrict__ K_r, const __half* __restrict__ K_i,
             const __half* __restrict__ V_r, const __half* __restrict__ V_i,
             __half* __restrict__ Or, __half* __restrict__ Oi)
{
    const int bh = blockIdx.y;
    const int tile = blockIdx.x;
    const int bm = tile * 128;
    const size_t off = (size_t)(bh >> 4) * Ln * Dn + (size_t)(bh & 15) * HDn;
    extern __shared__ char smemc[];
    const uint32_t sb = smem_u32(smemc);
    const uint32_t qb = sb;

    const int tid = threadIdx.x;
    const int wid = tid >> 5, lane = tid & 31;
    const int g = lane >> 2, t4 = lane & 3;
    const int row8 = tid >> 3, c8 = (tid & 7) * 8;

#pragma unroll
    for (int j = 0; j < 4; j++) {
        const int row = row8 + j * 32;
        const uint32_t o = (uint32_t)((row * FLD + c8) * 2);
        const size_t gq = off + (size_t)(bm + row) * Dn + c8;
        CP16(qb + o,          Q_r + gq);
        CP16(qb + FQT_B + o,  Q_i + gq);
    }
    auto prefetch_kv = [&](int kt) {
        const uint32_t dst = sb + 2*FQT_B + (uint32_t)((kt & 1) * FKV_B);
#pragma unroll
        for (int j = 0; j < 4; j++) {
            const int row = row8 + j * 32;
            const uint32_t o = (uint32_t)((row * FLD + c8) * 2);
            const size_t gk = off + (size_t)(kt*128 + row) * Dn + c8;
            CP16(dst + o,           K_r + gk);
            CP16(dst + FQT_B + o,   K_i + gk);
            CP16(dst + 2*FQT_B + o, V_r + gk);
            CP16(dst + 3*FQT_B + o, V_i + gk);
        }
    };
    prefetch_kv(0);
    CP_COMMIT();
    CP_WAIT0();
    __syncthreads();

    const uint32_t aq_base = (uint32_t)(((wid*16 + (lane & 15)) * FLD + (lane >> 4) * 8) * 2);
    uint32_t aqr[4][4], aqi[4][4];
#pragma unroll
    for (int ks = 0; ks < 4; ks++) {
        LDSM4(aqr[ks], qb + aq_base + (uint32_t)(ks * 32));
        LDSM4(aqi[ks], qb + FQT_B + aq_base + (uint32_t)(ks * 32));
    }

    const uint32_t bk_base = (uint32_t)((((lane & 7) + ((lane >> 4) ? 8 : 0)) * FLD
                                         + ((lane >> 3) & 1) * 8) * 2);
    const uint32_t bv_base = (uint32_t)((((lane & 7) + ((lane >> 3) & 1) * 8) * FLD
                                         + (lane >> 4) * 8) * 2);

    float oR[8][4], oI[8][4];
#pragma unroll
    for (int nt = 0; nt < 8; nt++)
#pragma unroll
        for (int r = 0; r < 4; r++) { oR[nt][r] = 0.f; oI[nt][r] = 0.f; }
    float m0 = -1e30f, m1 = -1e30f, s0 = 0.f, s1 = 0.f;

    const int row0 = bm + wid*16 + g;
    const int row1 = row0 + 8;

    for (int kt = 0; kt <= tile; kt++) {
        if (kt < tile) { prefetch_kv(kt + 1); CP_COMMIT(); }
        const uint32_t kvb = sb + 2*FQT_B + (uint32_t)((kt & 1) * FKV_B);

        float sacc[16][4];
#pragma unroll
        for (int nt = 0; nt < 16; nt++)
#pragma unroll
            for (int r = 0; r < 4; r++) sacc[nt][r] = 0.f;
#pragma unroll
        for (int ks = 0; ks < 4; ks++) {
            const uint32_t ko = (uint32_t)(ks * 32);
#pragma unroll
            for (int ng = 0; ng < 8; ng++) {
                const uint32_t bo = kvb + bk_base + (uint32_t)(ng * 16 * FLD * 2) + ko;
                uint32_t tkr[4], tki[4];
                LDSM4(tkr, bo);
                LDSM4(tki, bo + FQT_B);
                uint32_t blo[2] = {tkr[0], tkr[1]}, bhi[2] = {tkr[2], tkr[3]};
                MMA_F16(sacc[2*ng],   aqr[ks], blo);
                MMA_F16(sacc[2*ng+1], aqr[ks], bhi);
                blo[0] = tki[0]; blo[1] = tki[1]; bhi[0] = tki[2]; bhi[1] = tki[3];
                MMA_F16(sacc[2*ng],   aqi[ks], blo);
                MMA_F16(sacc[2*ng+1], aqi[ks], bhi);
            }
        }
        if (kt == tile) {
#pragma unroll
            for (int nt = 0; nt < 16; nt++) {
                const int c0 = kt*128 + nt*8 + 2*t4;
                sacc[nt][0] = (c0   <= row0) ? sacc[nt][0]*SCALEc : -1e30f;
                sacc[nt][1] = (c0+1 <= row0) ? sacc[nt][1]*SCALEc : -1e30f;
                sacc[nt][2] = (c0   <= row1) ? sacc[nt][2]*SCALEc : -1e30f;
                sacc[nt][3] = (c0+1 <= row1) ? sacc[nt][3]*SCALEc : -1e30f;
            }
        } else {
#pragma unroll
            for (int nt = 0; nt < 16; nt++)
#pragma unroll
                for (int r = 0; r < 4; r++) sacc[nt][r] *= SCALEc;
        }

        float mx0 = -1e30f, mx1 = -1e30f;
#pragma unroll
        for (int nt = 0; nt < 16; nt++) {
            mx0 = fmaxf(mx0, fmaxf(sacc[nt][0], sacc[nt][1]));
            mx1 = fmaxf(mx1, fmaxf(sacc[nt][2], sacc[nt][3]));
        }
        mx0 = fmaxf(mx0, __shfl_xor_sync(0xffffffffu, mx0, 1));
        mx0 = fmaxf(mx0, __shfl_xor_sync(0xffffffffu, mx0, 2));
        mx1 = fmaxf(mx1, __shfl_xor_sync(0xffffffffu, mx1, 1));
        mx1 = fmaxf(mx1, __shfl_xor_sync(0xffffffffu, mx1, 2));
        const float nm0 = fmaxf(m0, mx0), nm1 = fmaxf(m1, mx1);
        const float f0 = expf(m0 - nm0), f1 = expf(m1 - nm1);
        float sum0 = 0.f, sum1 = 0.f;
#pragma unroll
        for (int nt = 0; nt < 16; nt++) {
            sacc[nt][0] = expf(sacc[nt][0] - nm0);
            sacc[nt][1] = expf(sacc[nt][1] - nm0);
            sacc[nt][2] = expf(sacc[nt][2] - nm1);
            sacc[nt][3] = expf(sacc[nt][3] - nm1);
            sum0 += sacc[nt][0] + sacc[nt][1];
            sum1 += sacc[nt][2] + sacc[nt][3];
        }
        sum0 += __shfl_xor_sync(0xffffffffu, sum0, 1);
        sum0 += __shfl_xor_sync(0xffffffffu, sum0, 2);
        sum1 += __shfl_xor_sync(0xffffffffu, sum1, 1);
        sum1 += __shfl_xor_sync(0xffffffffu, sum1, 2);
        s0 = s0 * f0 + sum0;
        s1 = s1 * f1 + sum1;
        m0 = nm0; m1 = nm1;
#pragma unroll
        for (int nt = 0; nt < 8; nt++) {
            oR[nt][0] *= f0; oR[nt][1] *= f0; oR[nt][2] *= f1; oR[nt][3] *= f1;
            oI[nt][0] *= f0; oI[nt][1] *= f0; oI[nt][2] *= f1; oI[nt][3] *= f1;
        }

#pragma unroll
        for (int kc = 0; kc < 8; kc++) {
            uint32_t pa[4];
            pa[0] = packh2(sacc[2*kc][0],   sacc[2*kc][1]);
            pa[1] = packh2(sacc[2*kc][2],   sacc[2*kc][3]);
            pa[2] = packh2(sacc[2*kc+1][0], sacc[2*kc+1][1]);
            pa[3] = packh2(sacc[2*kc+1][2], sacc[2*kc+1][3]);
            const uint32_t vrow = bv_base + (uint32_t)(kc * 16 * FLD * 2);
#pragma unroll
            for (int vg = 0; vg < 2; vg++) {
                const uint32_t bo = kvb + vrow + (uint32_t)(vg * 32 * 2);
                uint32_t tvr[4], tvi[4];
                LDSM4T(tvr, bo + 2*FQT_B);
                LDSM4T(tvi, bo + 3*FQT_B);
                uint32_t blo[2] = {tvr[0], tvr[1]}, bhi[2] = {tvr[2], tvr[3]};
                MMA_F16(oR[4*vg],   pa, blo);
                MMA_F16(oR[4*vg+1], pa, bhi);
                blo[0] = tvi[0]; blo[1] = tvi[1]; bhi[0] = tvi[2]; bhi[1] = tvi[3];
                MMA_F16(oI[4*vg],   pa, blo);
                MMA_F16(oI[4*vg+1], pa, bhi);
            }
#pragma unroll
            for (int vg = 0; vg < 2; vg++) {
                const uint32_t bo = kvb + vrow + (uint32_t)((vg * 32 + 16) * 2);
                uint32_t tvr[4], tvi[4];
                LDSM4T(tvr, bo + 2*FQT_B);
                LDSM4T(tvi, bo + 3*FQT_B);
                uint32_t blo[2] = {tvr[0], tvr[1]}, bhi[2] = {tvr[2], tvr[3]};
                MMA_F16(oR[4*vg+2], pa, blo);
                MMA_F16(oR[4*vg+3], pa, bhi);
                blo[0] = tvi[0]; blo[1] = tvi[1]; bhi[0] = tvi[2]; bhi[1] = tvi[3];
                MMA_F16(oI[4*vg+2], pa, blo);
                MMA_F16(oI[4*vg+3], pa, bhi);
            }
        }
        if (kt < tile) CP_WAIT0();
        __syncthreads();
    }

    const float inv0 = 1.f / s0, inv1 = 1.f / s1;
#pragma unroll
    for (int nt = 0; nt < 8; nt++) {
        const int col = nt*8 + 2*t4;
        const size_t p0 = off + (size_t)row0 * Dn + col;
        const size_t p1 = off + (size_t)row1 * Dn + col;
        *(__half2*)(Or + p0) = __floats2half2_rn(oR[nt][0]*inv0, oR[nt][1]*inv0);
        *(__half2*)(Oi + p0) = __floats2half2_rn(oI[nt][0]*inv0, oI[nt][1]*inv0);
        *(__half2*)(Or + p1) = __floats2half2_rn(oR[nt][2]*inv1, oR[nt][3]*inv1);
        *(__half2*)(Oi + p1) = __floats2half2_rn(oI[nt][2]*inv1, oI[nt][3]*inv1);
    }
}

// ---------------- complex layernorm (fp32 in, half out) ---------------------
__global__ void cln16(const float* __restrict__ xr, const float* __restrict__ xi,
                      const float* __restrict__ gr, const float* __restrict__ gi,
                      const float* __restrict__ bre, const float* __restrict__ bim,
                      __half* __restrict__ outr, __half* __restrict__ outi)
{
    int row = blockIdx.x;
    const float* pr = xr + (size_t)row * Dn;
    const float* pi = xi + (size_t)row * Dn;
    __shared__ float s1[256], s2[256];
    int tid = threadIdx.x;
    float sr = 0.f, si = 0.f;
    for (int j = tid; j < Dn; j += 256) { sr += pr[j]; si += pi[j]; }
    s1[tid] = sr; s2[tid] = si;
    __syncthreads();
    for (int o = 128; o > 0; o >>= 1) {
        if (tid < o) { s1[tid] += s1[tid+o]; s2[tid] += s2[tid+o]; }
        __syncthreads();
    }
    float mr = s1[0] * (1.f/Dn), mi = s2[0] * (1.f/Dn);
    __syncthreads();
    float v = 0.f;
    for (int j = tid; j < Dn; j += 256) {
        float cr = pr[j] - mr, ci = pi[j] - mi;
        v += cr*cr + ci*ci;
    }
    s1[tid] = v;
    __syncthreads();
    for (int o = 128; o > 0; o >>= 1) {
        if (tid < o) s1[tid] += s1[tid+o];
        __syncthreads();
    }
    float inv = rsqrtf(s1[0] * (1.f/Dn) + EPSc);
    for (int j = tid; j < Dn; j += 256) {
        float nr = (pr[j]-mr)*inv, ni = (pi[j]-mi)*inv;
        outr[(size_t)row*Dn + j] = __float2half_rn(nr*gr[j] - ni*gi[j] + bre[j]);
        outi[(size_t)row*Dn + j] = __float2half_rn(nr*gi[j] + ni*gr[j] + bim[j]);
    }
}

// ---------------- RoPE (in place on half arrays) ----------------------------
__global__ void rope16(__half* __restrict__ xr, __half* __restrict__ xi)
{
    int idx = blockIdx.x * blockDim.x + threadIdx.x;
    int j = idx & 31;
    int t = idx >> 5;
    int h = t & (Hn-1); t >>= 4;
    int l = t & (Ln-1);
    int b = t >> 10;
    size_t base = ((size_t)(b*Ln + l)) * Dn + h * HDn;
    double invf = exp(-((double)(2*j) / (double)HDn) * 9.210340371976184);
    double th = (double)l * invf;
    double sd, cd;
    sincos(th, &sd, &cd);
    float c = (float)cd, s = (float)sd;
    float a0 = __half2float(xr[base+j]), a1 = __half2float(xr[base+j+32]);
    xr[base+j]    = __float2half_rn(a0*c - a1*s);
    xr[base+j+32] = __float2half_rn(a1*c + a0*s);
    float b0 = __half2float(xi[base+j]), b1 = __half2float(xi[base+j+32]);
    xi[base+j]    = __float2half_rn(b0*c - b1*s);
    xi[base+j+32] = __float2half_rn(b1*c + b0*s);
}

// ---------------- launch ----------------------------------------------------
extern "C" void kernel_launch(void* const* d_in, const int* in_sizes, int n_in,
                              void* d_out, int out_size)
{
    const float* x_r   = (const float*)d_in[0];
    const float* x_i   = (const float*)d_in[1];
    const float* Wq_r  = (const float*)d_in[2];
    const float* Wq_i  = (const float*)d_in[3];
    const float* Wk_r  = (const float*)d_in[4];
    const float* Wk_i  = (const float*)d_in[5];
    const float* Wv_r  = (const float*)d_in[6];
    const float* Wv_i  = (const float*)d_in[7];
    const float* Wo_r  = (const float*)d_in[8];
    const float* Wo_i  = (const float*)d_in[9];
    const float* bo_r  = (const float*)d_in[10];
    const float* bo_i  = (const float*)d_in[11];
    const float* ln1_gr = (const float*)d_in[12];
    const float* ln1_gi = (const float*)d_in[13];
    const float* ln1_br = (const float*)d_in[14];
    const float* ln1_bi = (const float*)d_in[15];
    const float* ln2_gr = (const float*)d_in[16];
    const float* ln2_gi = (const float*)d_in[17];
    const float* ln2_br = (const float*)d_in[18];
    const float* ln2_bi = (const float*)d_in[19];
    const float* W1_r  = (const float*)d_in[20];
    const float* W1_i  = (const float*)d_in[21];
    const float* b1_r  = (const float*)d_in[22];
    const float* b1_i  = (const float*)d_in[23];
    const float* W2_r  = (const float*)d_in[24];
    const float* W2_i  = (const float*)d_in[25];
    const float* b2_r  = (const float*)d_in[26];
    const float* b2_i  = (const float*)d_in[27];
    const float* mod_b = (const float*)d_in[28];
    float* out = (float*)d_out;

    __half *h16r, *h16i, *q16r, *q16i, *k16r, *k16i, *v16r, *v16i;
    __half *ao16r, *ao16i, *f16r, *f16i;
    __half *wq16r, *wq16i, *wk16r, *wk16i, *wv16r, *wv16i, *wo16r, *wo16i;
    __half *w116r, *w116i, *w216r, *w216i;
    float *ar, *ai;
    cudaGetSymbolAddress((void**)&h16r, g_h16r);  cudaGetSymbolAddress((void**)&h16i, g_h16i);
    cudaGetSymbolAddress((void**)&q16r, g_q16r);  cudaGetSymbolAddress((void**)&q16i, g_q16i);
    cudaGetSymbolAddress((void**)&k16r, g_k16r);  cudaGetSymbolAddress((void**)&k16i, g_k16i);
    cudaGetSymbolAddress((void**)&v16r, g_v16r);  cudaGetSymbolAddress((void**)&v16i, g_v16i);
    cudaGetSymbolAddress((void**)&ao16r, g_ao16r);cudaGetSymbolAddress((void**)&ao16i, g_ao16i);
    cudaGetSymbolAddress((void**)&ar, g_ar);      cudaGetSymbolAddress((void**)&ai, g_ai);
    cudaGetSymbolAddress((void**)&f16r, g_f16r);  cudaGetSymbolAddress((void**)&f16i, g_f16i);
    cudaGetSymbolAddress((void**)&wq16r, g_wq16r);cudaGetSymbolAddress((void**)&wq16i, g_wq16i);
    cudaGetSymbolAddress((void**)&wk16r, g_wk16r);cudaGetSymbolAddress((void**)&wk16i, g_wk16i);
    cudaGetSymbolAddress((void**)&wv16r, g_wv16r);cudaGetSymbolAddress((void**)&wv16i, g_wv16i);
    cudaGetSymbolAddress((void**)&wo16r, g_wo16r);cudaGetSymbolAddress((void**)&wo16i, g_wo16i);
    cudaGetSymbolAddress((void**)&w116r, g_w116r);cudaGetSymbolAddress((void**)&w116i, g_w116i);
    cudaGetSymbolAddress((void**)&w216r, g_w216r);cudaGetSymbolAddress((void**)&w216i, g_w216i);

    cudaFuncSetAttribute(hgemm,   cudaFuncAttributeMaxDynamicSharedMemorySize, SMEM_GEMM);
    cudaFuncSetAttribute(flash16, cudaFuncAttributeMaxDynamicSharedMemorySize, SMEM_FA);

    // 0. weight conversion to fp16
    const int n4d = Dn*Dn/4, n4h = HIDn*Dn/4;
    wprep16<<<n4d/256, 256>>>((const float4*)Wq_r, (const float4*)Wq_i, (__half2*)wq16r, (__half2*)wq16i, n4d);
    wprep16<<<n4d/256, 256>>>((const float4*)Wk_r, (const float4*)Wk_i, (__half2*)wk16r, (__half2*)wk16i, n4d);
    wprep16<<<n4d/256, 256>>>((const float4*)Wv_r, (const float4*)Wv_i, (__half2*)wv16r, (__half2*)wv16i, n4d);
    wprep16<<<n4d/256, 256>>>((const float4*)Wo_r, (const float4*)Wo_i, (__half2*)wo16r, (__half2*)wo16i, n4d);
    wprep16<<<n4h/256, 256>>>((const float4*)W1_r, (const float4*)W1_i, (__half2*)w116r, (__half2*)w116i, n4h);
    wprep16<<<n4h/256, 256>>>((const float4*)W2_r, (const float4*)W2_i, (__half2*)w216r, (__half2*)w216i, n4h);

    // 1. LN1 -> half
    cln16<<<Mn, 256>>>(x_r, x_i, ln1_gr, ln1_gi, ln1_br, ln1_bi, h16r, h16i);

    // 2. QKV projections (half in, half out)
    dim3 gproj(Dn/BNg, Mn/BMg);
    hgemm<<<gproj, 256, SMEM_GEMM>>>(h16r, h16i, wq16r, wq16i, nullptr, nullptr, q16r, q16i, Mn, Dn, Dn, nullptr, nullptr, nullptr, nullptr, nullptr);
    hgemm<<<gproj, 256, SMEM_GEMM>>>(h16r, h16i, wk16r, wk16i, nullptr, nullptr, k16r, k16i, Mn, Dn, Dn, nullptr, nullptr, nullptr, nullptr, nullptr);
    hgemm<<<gproj, 256, SMEM_GEMM>>>(h16r, h16i, wv16r, wv16i, nullptr, nullptr, v16r, v16i, Mn, Dn, Dn, nullptr, nullptr, nullptr, nullptr, nullptr);

    // 3. RoPE on Q and K (half in place)
    rope16<<<(Bn*Ln*Hn*32)/256, 256>>>(q16r, q16i);
    rope16<<<(Bn*Ln*Hn*32)/256, 256>>>(k16r, k16i);

    // 4. fused flash attention -> ao16
    flash16<<<dim3(Ln/128, Bn*Hn), 256, SMEM_FA>>>(q16r, q16i, k16r, k16i, v16r, v16i, ao16r, ao16i);

    // 5. out projection + bias + residual(x) -> fp32
    hgemm<<<gproj, 256, SMEM_GEMM>>>(ao16r, ao16i, wo16r, wo16i, ar, ai, nullptr, nullptr, Mn, Dn, Dn, bo_r, bo_i, x_r, x_i, nullptr);

    // 6. LN2 -> half
    cln16<<<Mn, 256>>>(ar, ai, ln2_gr, ln2_gi, ln2_br, ln2_bi, h16r, h16i);

    // 7. FC1 + bias + fused ModReLU -> half
    hgemm<<<dim3(HIDn/BNg, Mn/BMg), 256, SMEM_GEMM>>>(h16r, h16i, w116r, w116i, nullptr, nullptr, f16r, f16i, Mn, HIDn, Dn, b1_r, b1_i, nullptr, nullptr, mod_b);

    // 8. FC2 + bias + residual(ar/ai) -> output (fp32)
    hgemm<<<gproj, 256, SMEM_GEMM>>>(f16r, f16i, w216r, w216i, out, out + (size_t)Mn*Dn, nullptr, nullptr, Mn, Dn, HIDn, b2_r, b2_i, ar, ai, nullptr);
}